// round 4
// baseline (speedup 1.0000x reference)
#include <cuda_runtime.h>
#include <cuda_bf16.h>
#include <math.h>

// Problem constants
#define BATCH 2
#define SEQ   1024
#define HID   2048
#define NH    32
#define NKV   4
#define GRP   8
#define HD    128
#define NQKV  5120
#define TOK   (BATCH*SEQ)
#define SCALE 0.08838834764831845f
#define RMS_EPS 1e-6f

// -------------------- scratch -------------------------------------------
__device__ float g_qkv[TOK * NQKV];
__device__ float g_q[BATCH * NH * SEQ * HD];
__device__ float g_k[BATCH * NKV * SEQ * HD];
__device__ float g_v[BATCH * NKV * SEQ * HD];
__device__ float g_ctx[TOK * NH * HD];

__device__ __forceinline__ unsigned f2tf32(float x) {
    unsigned y;
    asm("cvt.rna.tf32.f32 %0, %1;" : "=r"(y) : "f"(x));
    return y;
}

__device__ __forceinline__ void mma_tf32(float c[4],
    unsigned a0, unsigned a1, unsigned a2, unsigned a3,
    unsigned b0, unsigned b1)
{
    asm volatile(
        "mma.sync.aligned.m16n8k8.row.col.f32.tf32.tf32.f32 "
        "{%0,%1,%2,%3}, {%4,%5,%6,%7}, {%8,%9}, {%0,%1,%2,%3};"
        : "+f"(c[0]), "+f"(c[1]), "+f"(c[2]), "+f"(c[3])
        : "r"(a0), "r"(a1), "r"(a2), "r"(a3), "r"(b0), "r"(b1));
}

// ---------------------------------------------------------------------------
// TF32 tensor-core GEMM (unchanged from R3 — known good)
// ---------------------------------------------------------------------------
__global__ __launch_bounds__(256) void gemm_tf32(
    const float* __restrict__ A, const float* __restrict__ B,
    float* __restrict__ C, int M, int N, int K)
{
    __shared__ unsigned As[128][36];
    __shared__ unsigned Bs[32][136];

    const int tid  = threadIdx.x;
    const int lane = tid & 31;
    const int wid  = tid >> 5;
    const int bm = blockIdx.y, bn = blockIdx.x;

    const int wm = (wid & 3) * 32;
    const int wn = (wid >> 2) * 64;

    const int arow = tid >> 1,  acol = (tid & 1) * 16;
    const int brow = tid >> 3,  bcol = (tid & 7) * 16;

    const float* Ag = A + (size_t)(bm * 128 + arow) * K + acol;
    const float* Bg = B + (size_t)brow * N + bn * 128 + bcol;

    const int qr = lane >> 2;
    const int ql = lane & 3;

    float acc[2][8][4];
#pragma unroll
    for (int i = 0; i < 2; i++)
#pragma unroll
        for (int j = 0; j < 8; j++)
#pragma unroll
            for (int c = 0; c < 4; c++) acc[i][j][c] = 0.f;

    for (int k0 = 0; k0 < K; k0 += 32) {
        float4 av[4], bv[4];
#pragma unroll
        for (int u = 0; u < 4; u++) {
            av[u] = *(const float4*)(Ag + k0 + u * 4);
            bv[u] = *(const float4*)(Bg + (size_t)k0 * N + u * 4);
        }
        __syncthreads();
#pragma unroll
        for (int u = 0; u < 4; u++) {
            As[arow][acol + u * 4 + 0] = f2tf32(av[u].x);
            As[arow][acol + u * 4 + 1] = f2tf32(av[u].y);
            As[arow][acol + u * 4 + 2] = f2tf32(av[u].z);
            As[arow][acol + u * 4 + 3] = f2tf32(av[u].w);
            Bs[brow][bcol + u * 4 + 0] = f2tf32(bv[u].x);
            Bs[brow][bcol + u * 4 + 1] = f2tf32(bv[u].y);
            Bs[brow][bcol + u * 4 + 2] = f2tf32(bv[u].z);
            Bs[brow][bcol + u * 4 + 3] = f2tf32(bv[u].w);
        }
        __syncthreads();

#pragma unroll
        for (int kk = 0; kk < 4; kk++) {
            const int kb = kk * 8 + ql;
            unsigned a[2][4];
#pragma unroll
            for (int i = 0; i < 2; i++) {
                const int r = wm + i * 16 + qr;
                a[i][0] = As[r    ][kb    ];
                a[i][1] = As[r + 8][kb    ];
                a[i][2] = As[r    ][kb + 4];
                a[i][3] = As[r + 8][kb + 4];
            }
#pragma unroll
            for (int j = 0; j < 8; j++) {
                const int n = wn + j * 8 + qr;
                unsigned b0 = Bs[kb    ][n];
                unsigned b1 = Bs[kb + 4][n];
#pragma unroll
                for (int i = 0; i < 2; i++)
                    mma_tf32(acc[i][j], a[i][0], a[i][1], a[i][2], a[i][3], b0, b1);
            }
        }
    }

#pragma unroll
    for (int i = 0; i < 2; i++) {
        const int r0 = bm * 128 + wm + i * 16 + qr;
#pragma unroll
        for (int j = 0; j < 8; j++) {
            const int c = bn * 128 + wn + j * 8 + ql * 2;
            *(float2*)(C + (size_t)r0 * N + c)       = make_float2(acc[i][j][0], acc[i][j][1]);
            *(float2*)(C + (size_t)(r0 + 8) * N + c) = make_float2(acc[i][j][2], acc[i][j][3]);
        }
    }
}

// ---------------------------------------------------------------------------
// RMSNorm + RoPE + split (unchanged)
// ---------------------------------------------------------------------------
__global__ __launch_bounds__(128) void norm_rope_kernel(
    const float* __restrict__ qkv, const float* __restrict__ cosb,
    const float* __restrict__ sinb, const float* __restrict__ qw,
    const float* __restrict__ kw,
    float* __restrict__ Q, float* __restrict__ K, float* __restrict__ V)
{
    const int token = blockIdx.x;
    const int slot  = blockIdx.y;
    const int d     = threadIdx.x;
    const int b = token / SEQ, s = token % SEQ;

    const float x = qkv[(size_t)token * NQKV + slot * HD + d];

    if (slot >= 36) {
        const int kh = slot - 36;
        V[((size_t)(b * NKV + kh) * SEQ + s) * HD + d] = x;
        return;
    }

    __shared__ float xn[HD];
    __shared__ float red[4];

    float ss = x * x;
#pragma unroll
    for (int o = 16; o > 0; o >>= 1) ss += __shfl_xor_sync(0xffffffffu, ss, o);
    if ((d & 31) == 0) red[d >> 5] = ss;
    __syncthreads();
    const float tot = red[0] + red[1] + red[2] + red[3];
    const float inv = rsqrtf(tot * (1.0f / HD) + RMS_EPS);

    const float* w = (slot < 32) ? qw : kw;
    const float v = x * inv * w[d];
    xn[d] = v;
    __syncthreads();

    const float rot = (d < 64) ? -xn[d + 64] : xn[d - 64];
    const float c  = cosb[(size_t)s * HD + d];
    const float sn = sinb[(size_t)s * HD + d];
    const float out = v * c + rot * sn;

    if (slot < 32)
        Q[((size_t)(b * NH + slot) * SEQ + s) * HD + d] = out;
    else
        K[((size_t)(b * NKV + (slot - 32)) * SEQ + s) * HD + d] = out;
}

// ---------------------------------------------------------------------------
// Tensor-core causal GQA flash attention.
// 64 q-rows x 64 kv per tile, 256 threads (8 warps).
// QK^T: tf32x3 (hi/lo split of Q and K) for fp32-grade logits.
// P*V : plain tf32.
// Warp layout QK: 4x2 grid of 16x32 tiles; PV: 4x2 grid of 16x64 tiles.
// ---------------------------------------------------------------------------
#define AST 132   // Q/K/V smem row stride (words); 132 % 32 == 4 -> conflict-free frags
#define SST 68    // score smem row stride
__global__ __launch_bounds__(256) void attn_tc_kernel(
    const float* __restrict__ Q, const float* __restrict__ K,
    const float* __restrict__ V)
{
    extern __shared__ float sm[];
    unsigned* Qh = (unsigned*)sm;            // 64*AST
    unsigned* Ql = Qh + 64 * AST;
    unsigned* Kh = Ql + 64 * AST;
    unsigned* Kl = Kh + 64 * AST;
    unsigned* Vs = Kl + 64 * AST;            // 64*AST (tf32)
    float*    Ss = (float*)(Vs + 64 * AST);  // 64*SST
    float*   m_s = Ss + 64 * SST;
    float*   l_s = m_s + 64;
    float*  sc_s = l_s + 64;

    const int m_tile = (gridDim.x - 1) - blockIdx.x;   // heavy tiles first
    const int h = blockIdx.y, b = blockIdx.z;
    const int kh = h / GRP;
    const int tid = threadIdx.x;
    const int lane = tid & 31, wid = tid >> 5;
    const int qr = lane >> 2, ql = lane & 3;
    const int mband  = (wid & 3) * 16;
    const int nband  = (wid >> 2) * 32;   // QK
    const int nband2 = (wid >> 2) * 64;   // PV
    const int m0 = m_tile * 64;

    const float* Qbase = Q + ((size_t)(b * NH + h) * SEQ + m0) * HD;
    const float* Kbase = K + ((size_t)(b * NKV + kh) * SEQ) * HD;
    const float* Vbase = V + ((size_t)(b * NKV + kh) * SEQ) * HD;

    // load Q tile, pre-scale by SCALE, split hi/lo tf32
    for (int i = tid; i < 64 * 32; i += 256) {
        const int r = i >> 5, c = (i & 31) * 4;
        float4 q4 = *(const float4*)(Qbase + (size_t)r * HD + c);
        float xs[4] = {q4.x * SCALE, q4.y * SCALE, q4.z * SCALE, q4.w * SCALE};
#pragma unroll
        for (int u = 0; u < 4; u++) {
            unsigned hi = f2tf32(xs[u]);
            Qh[r * AST + c + u] = hi;
            Ql[r * AST + c + u] = f2tf32(xs[u] - __uint_as_float(hi));
        }
    }
    if (tid < 64) { m_s[tid] = -1e30f; l_s[tid] = 0.f; sc_s[tid] = 0.f; }

    float oacc[8][4];
#pragma unroll
    for (int j = 0; j < 8; j++)
#pragma unroll
        for (int c = 0; c < 4; c++) oacc[j][c] = 0.f;

    const int row0 = mband + qr, row1 = mband + qr + 8;

    for (int t = 0; t <= m_tile; ++t) {
        const int n0 = t * 64;
        // load K (hi/lo) and V (tf32) tiles
        for (int i = tid; i < 64 * 32; i += 256) {
            const int r = i >> 5, c = (i & 31) * 4;
            float4 k4 = *(const float4*)(Kbase + (size_t)(n0 + r) * HD + c);
            float4 v4 = *(const float4*)(Vbase + (size_t)(n0 + r) * HD + c);
            float kx[4] = {k4.x, k4.y, k4.z, k4.w};
            float vx[4] = {v4.x, v4.y, v4.z, v4.w};
#pragma unroll
            for (int u = 0; u < 4; u++) {
                unsigned hi = f2tf32(kx[u]);
                Kh[r * AST + c + u] = hi;
                Kl[r * AST + c + u] = f2tf32(kx[u] - __uint_as_float(hi));
                Vs[r * AST + c + u] = f2tf32(vx[u]);
            }
        }
        __syncthreads();

        // QK^T: tf32x3
        float sacc[4][4];
#pragma unroll
        for (int j = 0; j < 4; j++)
#pragma unroll
            for (int c = 0; c < 4; c++) sacc[j][c] = 0.f;

#pragma unroll
        for (int k = 0; k < 16; k++) {
            const int kb = k * 8 + ql;
            unsigned ah0 = Qh[row0 * AST + kb],     ah1 = Qh[row1 * AST + kb];
            unsigned ah2 = Qh[row0 * AST + kb + 4], ah3 = Qh[row1 * AST + kb + 4];
            unsigned al0 = Ql[row0 * AST + kb],     al1 = Ql[row1 * AST + kb];
            unsigned al2 = Ql[row0 * AST + kb + 4], al3 = Ql[row1 * AST + kb + 4];
#pragma unroll
            for (int j = 0; j < 4; j++) {
                const int n = nband + j * 8 + qr;
                unsigned bh0 = Kh[n * AST + kb], bh1 = Kh[n * AST + kb + 4];
                unsigned bl0 = Kl[n * AST + kb], bl1 = Kl[n * AST + kb + 4];
                mma_tf32(sacc[j], ah0, ah1, ah2, ah3, bh0, bh1);
                mma_tf32(sacc[j], al0, al1, al2, al3, bh0, bh1);
                mma_tf32(sacc[j], ah0, ah1, ah2, ah3, bl0, bl1);
            }
        }

        // masked writeback (Q was pre-scaled)
#pragma unroll
        for (int j = 0; j < 4; j++) {
            const int cg = nband + j * 8 + 2 * ql;   // tile-local key col
            const int k0g = n0 + cg;
            const int q0g = m0 + row0, q1g = m0 + row1;
            Ss[row0 * SST + cg]     = (k0g     <= q0g) ? sacc[j][0] : -1e30f;
            Ss[row0 * SST + cg + 1] = (k0g + 1 <= q0g) ? sacc[j][1] : -1e30f;
            Ss[row1 * SST + cg]     = (k0g     <= q1g) ? sacc[j][2] : -1e30f;
            Ss[row1 * SST + cg + 1] = (k0g + 1 <= q1g) ? sacc[j][3] : -1e30f;
        }
        __syncthreads();

        // online softmax: 4 threads/row
        {
            const int sr = tid >> 2;
            const int sl = tid & 3;
            const int cb = sl * 16;
            float mx = -1e30f;
#pragma unroll
            for (int c = 0; c < 16; c++)
                mx = fmaxf(mx, Ss[sr * SST + cb + c]);
            mx = fmaxf(mx, __shfl_xor_sync(0xffffffffu, mx, 1));
            mx = fmaxf(mx, __shfl_xor_sync(0xffffffffu, mx, 2));
            const float mo = m_s[sr];
            mx = fmaxf(mx, mo);
            float l = 0.f;
#pragma unroll
            for (int c = 0; c < 16; c++) {
                const float p = __expf(Ss[sr * SST + cb + c] - mx);
                Ss[sr * SST + cb + c] = p;
                l += p;
            }
            l += __shfl_xor_sync(0xffffffffu, l, 1);
            l += __shfl_xor_sync(0xffffffffu, l, 2);
            if (sl == 0) {
                const float scl = __expf(mo - mx);
                l_s[sr] = l_s[sr] * scl + l;
                m_s[sr] = mx;
                sc_s[sr] = scl;
            }
        }
        __syncthreads();

        // rescale + P*V (plain tf32)
        {
            const float scl0 = sc_s[row0], scl1 = sc_s[row1];
#pragma unroll
            for (int j = 0; j < 8; j++) {
                oacc[j][0] *= scl0; oacc[j][1] *= scl0;
                oacc[j][2] *= scl1; oacc[j][3] *= scl1;
            }
        }
#pragma unroll
        for (int k = 0; k < 8; k++) {
            const int kb = k * 8 + ql;
            unsigned a0 = f2tf32(Ss[row0 * SST + kb]);
            unsigned a1 = f2tf32(Ss[row1 * SST + kb]);
            unsigned a2 = f2tf32(Ss[row0 * SST + kb + 4]);
            unsigned a3 = f2tf32(Ss[row1 * SST + kb + 4]);
#pragma unroll
            for (int j = 0; j < 8; j++) {
                const int n = nband2 + j * 8 + qr;
                unsigned b0 = Vs[kb * AST + n];
                unsigned b1 = Vs[(kb + 4) * AST + n];
                mma_tf32(oacc[j], a0, a1, a2, a3, b0, b1);
            }
        }
        __syncthreads();
    }

    // epilogue: normalize and write ctx[b, s, h*HD + d]
    const float invl0 = 1.0f / l_s[row0];
    const float invl1 = 1.0f / l_s[row1];
#pragma unroll
    for (int j = 0; j < 8; j++) {
        const int col = nband2 + j * 8 + 2 * ql;
        float* o0 = g_ctx + ((size_t)b * SEQ + m0 + row0) * (NH * HD) + h * HD + col;
        float* o1 = g_ctx + ((size_t)b * SEQ + m0 + row1) * (NH * HD) + h * HD + col;
        *(float2*)o0 = make_float2(oacc[j][0] * invl0, oacc[j][1] * invl0);
        *(float2*)o1 = make_float2(oacc[j][2] * invl1, oacc[j][3] * invl1);
    }
}

// ---------------------------------------------------------------------------
extern "C" void kernel_launch(void* const* d_in, const int* in_sizes, int n_in,
                              void* d_out, int out_size)
{
    const float* hidden = (const float*)d_in[0];
    const float* cosb   = (const float*)d_in[1];
    const float* sinb   = (const float*)d_in[2];
    const float* w_qkv  = (const float*)d_in[3];
    const float* q_w    = (const float*)d_in[4];
    const float* k_w    = (const float*)d_in[5];
    const float* w_o    = (const float*)d_in[6];
    float* out = (float*)d_out;

    float *qkv_p, *q_p, *k_p, *v_p, *ctx_p;
    cudaGetSymbolAddress((void**)&qkv_p, g_qkv);
    cudaGetSymbolAddress((void**)&q_p,   g_q);
    cudaGetSymbolAddress((void**)&k_p,   g_k);
    cudaGetSymbolAddress((void**)&v_p,   g_v);
    cudaGetSymbolAddress((void**)&ctx_p, g_ctx);

    // attention smem: 5 * 64*AST words (Qh,Ql,Kh,Kl,Vs) + 64*SST + 192
    const int attn_smem = (5 * 64 * AST + 64 * SST + 192) * 4;
    cudaFuncSetAttribute(attn_tc_kernel, cudaFuncAttributeMaxDynamicSharedMemorySize, attn_smem);

    // 1) QKV projection (tf32 tensor cores)
    gemm_tf32<<<dim3(NQKV / 128, TOK / 128), 256>>>(hidden, w_qkv, qkv_p, TOK, NQKV, HID);

    // 2) RMSNorm + RoPE + split
    norm_rope_kernel<<<dim3(TOK, 40), 128>>>(qkv_p, cosb, sinb, q_w, k_w, q_p, k_p, v_p);

    // 3) causal GQA attention (tensor cores)
    attn_tc_kernel<<<dim3(SEQ / 64, NH, BATCH), 256, attn_smem>>>(q_p, k_p, v_p);

    // 4) output projection (tf32 tensor cores)
    gemm_tf32<<<dim3(HID / 128, TOK / 128), 256>>>(ctx_p, w_o, out, TOK, HID, NH * HD);

    (void)in_sizes; (void)n_in; (void)out_size;
}

// round 5
// speedup vs baseline: 1.2809x; 1.2809x over previous
#include <cuda_runtime.h>
#include <cuda_bf16.h>
#include <math.h>

// Problem constants
#define BATCH 2
#define SEQ   1024
#define HID   2048
#define NH    32
#define NKV   4
#define GRP   8
#define HD    128
#define NQKV  5120
#define TOK   (BATCH*SEQ)
#define SCALE 0.08838834764831845f
#define RMS_EPS 1e-6f

// -------------------- scratch -------------------------------------------
__device__ float    g_qkv[TOK * NQKV];
__device__ float    g_q[BATCH * NH * SEQ * HD];
__device__ float    g_k[BATCH * NKV * SEQ * HD];
__device__ float    g_v[BATCH * NKV * SEQ * HD];
__device__ float    g_ctx[TOK * NH * HD];
__device__ unsigned g_wqkv_t[NQKV * HID];      // W_qkv^T as tf32 [5120][2048]
__device__ unsigned g_wo_t[HID * (NH * HD)];   // W_o^T  as tf32 [2048][4096]

__device__ __forceinline__ unsigned f2tf32(float x) {
    unsigned y;
    asm("cvt.rna.tf32.f32 %0, %1;" : "=r"(y) : "f"(x));
    return y;
}

__device__ __forceinline__ void mma_tf32(float c[4],
    unsigned a0, unsigned a1, unsigned a2, unsigned a3,
    unsigned b0, unsigned b1)
{
    asm volatile(
        "mma.sync.aligned.m16n8k8.row.col.f32.tf32.tf32.f32 "
        "{%0,%1,%2,%3}, {%4,%5,%6,%7}, {%8,%9}, {%0,%1,%2,%3};"
        : "+f"(c[0]), "+f"(c[1]), "+f"(c[2]), "+f"(c[3])
        : "r"(a0), "r"(a1), "r"(a2), "r"(a3), "r"(b0), "r"(b1));
}

__device__ __forceinline__ void ldsm_x4(unsigned r[4], unsigned addr) {
    asm volatile("ldmatrix.sync.aligned.m8n8.x4.shared.b16 {%0,%1,%2,%3}, [%4];"
                 : "=r"(r[0]), "=r"(r[1]), "=r"(r[2]), "=r"(r[3]) : "r"(addr));
}

// ---------------------------------------------------------------------------
// Transpose + tf32-convert: out[n][k] = tf32(in[k][n]).  in: [K][N] float.
// block (32,8), grid (N/32, K/32).
// ---------------------------------------------------------------------------
__global__ __launch_bounds__(256) void transpose_tf32(
    const float* __restrict__ in, unsigned* __restrict__ out, int K, int N)
{
    __shared__ unsigned t[32][33];
    const int tx = threadIdx.x, ty = threadIdx.y;
    const int n0 = blockIdx.x * 32, k0 = blockIdx.y * 32;
#pragma unroll
    for (int i = 0; i < 4; i++) {
        const int k = k0 + ty + i * 8;
        t[ty + i * 8][tx] = f2tf32(in[(size_t)k * N + n0 + tx]);
    }
    __syncthreads();
#pragma unroll
    for (int i = 0; i < 4; i++) {
        const int n = n0 + ty + i * 8;
        out[(size_t)n * K + k0 + tx] = t[tx][ty + i * 8];
    }
}

// ---------------------------------------------------------------------------
// NT tf32 GEMM: C[M,N] = A[M,K] @ Bt[N,K]^T.
// A: float row-major (cvt at staging). Bt: pre-converted tf32 u32, n-major.
// 128x128 tile, BK=32, 256 threads / 8 warps, warp 32x64, m16n8k8.
// Both smem operands [128][36] (pad-36 => LDSM + STS.128 conflict-free).
// Double-buffered: one __syncthreads per k-iter.
// ---------------------------------------------------------------------------
#define GS 36
#define TSW (128 * GS)          // words per stage per operand
#define STAGE_B (TSW * 4)       // bytes per stage

__global__ __launch_bounds__(256) void gemm_nt(
    const float* __restrict__ A, const unsigned* __restrict__ Bt,
    float* __restrict__ C, int M, int N, int K)
{
    extern __shared__ unsigned sh[];   // [2 stages A][2 stages B]
    unsigned* Asm = sh;                // stage s at Asm + s*TSW
    unsigned* Bsm = sh + 2 * TSW;

    const int tid  = threadIdx.x;
    const int lane = tid & 31;
    const int wid  = tid >> 5;
    const int bm = blockIdx.y, bn = blockIdx.x;

    const int wm = (wid & 3) * 32;
    const int wn = (wid >> 2) * 64;
    const int qr = lane >> 2, ql = lane & 3;

    // staging indices (both operands identical pattern)
    const int srow = tid >> 1, scol = (tid & 1) * 16;

    const float*    Ag = A  + (size_t)(bm * 128 + srow) * K + scol;
    const unsigned* Bg = Bt + (size_t)(bn * 128 + srow) * K + scol;

    // ldmatrix per-lane byte offsets (within a stage)
    const unsigned a_base = (unsigned)__cvta_generic_to_shared(Asm);
    const unsigned b_base = (unsigned)__cvta_generic_to_shared(Bsm);
    // A: row = wm + i*16 + (lane&7) + (lane&8), col = (lane>>4)*4
    unsigned a_off[2];
#pragma unroll
    for (int i = 0; i < 2; i++)
        a_off[i] = ((wm + i * 16 + (lane & 7) + (lane & 8)) * GS +
                    ((lane >> 4) << 2)) * 4;
    // B: row = wn + jp*16 + (lane&7) + ((lane&16)>>1), col = ((lane>>3)&1)*4
    unsigned b_off[4];
#pragma unroll
    for (int jp = 0; jp < 4; jp++)
        b_off[jp] = ((wn + jp * 16 + (lane & 7) + ((lane & 16) >> 1)) * GS +
                     (((lane >> 3) & 1) << 2)) * 4;

    float acc[2][8][4];
#pragma unroll
    for (int i = 0; i < 2; i++)
#pragma unroll
        for (int j = 0; j < 8; j++)
#pragma unroll
            for (int c = 0; c < 4; c++) acc[i][j][c] = 0.f;

    const int niter = K >> 5;
    uint4 astg[4], bstg[4];

    // prologue: load iter 0, store stage 0
#pragma unroll
    for (int u = 0; u < 4; u++) {
        float4 av = *(const float4*)(Ag + u * 4);
        astg[u] = make_uint4(f2tf32(av.x), f2tf32(av.y), f2tf32(av.z), f2tf32(av.w));
        bstg[u] = *(const uint4*)(Bg + u * 4);
    }
#pragma unroll
    for (int u = 0; u < 4; u++) {
        *(uint4*)&Asm[srow * GS + scol + u * 4] = astg[u];
        *(uint4*)&Bsm[srow * GS + scol + u * 4] = bstg[u];
    }

    for (int it = 0; it < niter; ++it) {
        __syncthreads();
        const int cur = it & 1;
        const bool more = (it + 1) < niter;
        if (more) {
            const int k0 = (it + 1) << 5;
#pragma unroll
            for (int u = 0; u < 4; u++) {
                float4 av = *(const float4*)(Ag + k0 + u * 4);
                astg[u] = make_uint4(f2tf32(av.x), f2tf32(av.y), f2tf32(av.z), f2tf32(av.w));
                bstg[u] = *(const uint4*)(Bg + k0 + u * 4);
            }
        }

        const unsigned a_st = a_base + cur * STAGE_B;
        const unsigned b_st = b_base + cur * STAGE_B;
#pragma unroll
        for (int kk = 0; kk < 4; kk++) {
            const unsigned koff = kk * 32;   // 8 words
            unsigned a[2][4];
            ldsm_x4(a[0], a_st + a_off[0] + koff);
            ldsm_x4(a[1], a_st + a_off[1] + koff);
#pragma unroll
            for (int jp = 0; jp < 4; jp++) {
                unsigned bfr[4];
                ldsm_x4(bfr, b_st + b_off[jp] + koff);
#pragma unroll
                for (int i = 0; i < 2; i++) {
                    mma_tf32(acc[i][2 * jp],     a[i][0], a[i][1], a[i][2], a[i][3], bfr[0], bfr[1]);
                    mma_tf32(acc[i][2 * jp + 1], a[i][0], a[i][1], a[i][2], a[i][3], bfr[2], bfr[3]);
                }
            }
        }

        if (more) {
            const int nxt = (it + 1) & 1;
            unsigned* Ad = Asm + nxt * TSW;
            unsigned* Bd = Bsm + nxt * TSW;
#pragma unroll
            for (int u = 0; u < 4; u++) {
                *(uint4*)&Ad[srow * GS + scol + u * 4] = astg[u];
                *(uint4*)&Bd[srow * GS + scol + u * 4] = bstg[u];
            }
        }
    }

    // epilogue (same fragment layout as R3)
#pragma unroll
    for (int i = 0; i < 2; i++) {
        const int r0 = bm * 128 + wm + i * 16 + qr;
#pragma unroll
        for (int j = 0; j < 8; j++) {
            const int c = bn * 128 + wn + j * 8 + ql * 2;
            *(float2*)(C + (size_t)r0 * N + c)       = make_float2(acc[i][j][0], acc[i][j][1]);
            *(float2*)(C + (size_t)(r0 + 8) * N + c) = make_float2(acc[i][j][2], acc[i][j][3]);
        }
    }
}

// ---------------------------------------------------------------------------
// RMSNorm + RoPE + split (unchanged, measured good)
// ---------------------------------------------------------------------------
__global__ __launch_bounds__(128) void norm_rope_kernel(
    const float* __restrict__ qkv, const float* __restrict__ cosb,
    const float* __restrict__ sinb, const float* __restrict__ qw,
    const float* __restrict__ kw,
    float* __restrict__ Q, float* __restrict__ K, float* __restrict__ V)
{
    const int token = blockIdx.x;
    const int slot  = blockIdx.y;
    const int d     = threadIdx.x;
    const int b = token / SEQ, s = token % SEQ;

    const float x = qkv[(size_t)token * NQKV + slot * HD + d];

    if (slot >= 36) {
        const int kh = slot - 36;
        V[((size_t)(b * NKV + kh) * SEQ + s) * HD + d] = x;
        return;
    }

    __shared__ float xn[HD];
    __shared__ float red[4];

    float ss = x * x;
#pragma unroll
    for (int o = 16; o > 0; o >>= 1) ss += __shfl_xor_sync(0xffffffffu, ss, o);
    if ((d & 31) == 0) red[d >> 5] = ss;
    __syncthreads();
    const float tot = red[0] + red[1] + red[2] + red[3];
    const float inv = rsqrtf(tot * (1.0f / HD) + RMS_EPS);

    const float* w = (slot < 32) ? qw : kw;
    const float v = x * inv * w[d];
    xn[d] = v;
    __syncthreads();

    const float rot = (d < 64) ? -xn[d + 64] : xn[d - 64];
    const float c  = cosb[(size_t)s * HD + d];
    const float sn = sinb[(size_t)s * HD + d];
    const float out = v * c + rot * sn;

    if (slot < 32)
        Q[((size_t)(b * NH + slot) * SEQ + s) * HD + d] = out;
    else
        K[((size_t)(b * NKV + (slot - 32)) * SEQ + s) * HD + d] = out;
}

// ---------------------------------------------------------------------------
// Causal GQA flash attention — R3 FFMA version (measured ~1050us, reverted)
// ---------------------------------------------------------------------------
#define QS_STRIDE 129
#define SS_STRIDE 65
__global__ __launch_bounds__(256) void attn_kernel(
    const float* __restrict__ Q, const float* __restrict__ K,
    const float* __restrict__ V)
{
    extern __shared__ float sm[];
    float* Qs  = sm;
    float* Ks  = Qs + 64 * QS_STRIDE;
    float* Vs  = Ks + 64 * QS_STRIDE;
    float* Ss  = Vs + 64 * 128;
    float* m_s = Ss + 64 * SS_STRIDE;
    float* l_s = m_s + 64;
    float* sc_s = l_s + 64;

    const int m_tile = (gridDim.x - 1) - blockIdx.x;   // heavy tiles first
    const int h = blockIdx.y;
    const int b = blockIdx.z;
    const int kh = h / GRP;
    const int tid = threadIdx.x;
    const int m0 = m_tile * 64;

    const float* Qbase = Q + ((size_t)(b * NH + h) * SEQ + m0) * HD;
    const float* Kbase = K + ((size_t)(b * NKV + kh) * SEQ) * HD;
    const float* Vbase = V + ((size_t)(b * NKV + kh) * SEQ) * HD;

    for (int i = tid; i < 64 * 32; i += 256) {
        int r = i >> 5, c4 = (i & 31) * 4;
        float4 q4 = *(const float4*)(Qbase + (size_t)r * HD + c4);
        Qs[r * QS_STRIDE + c4 + 0] = q4.x;
        Qs[r * QS_STRIDE + c4 + 1] = q4.y;
        Qs[r * QS_STRIDE + c4 + 2] = q4.z;
        Qs[r * QS_STRIDE + c4 + 3] = q4.w;
    }
    if (tid < 64) { m_s[tid] = -1e30f; l_s[tid] = 0.f; }

    const int tr = tid >> 4, tc = tid & 15;
    const int r0 = tr * 4;
    const int cS0 = tc * 4;
    const int cO0 = tc * 8;

    float acc[4][8];
#pragma unroll
    for (int i = 0; i < 4; i++)
#pragma unroll
        for (int j = 0; j < 8; j++) acc[i][j] = 0.f;

    __syncthreads();

    const int ntiles = m_tile + 1;
    for (int t = 0; t < ntiles; ++t) {
        const int n0 = t * 64;
        for (int i = tid; i < 64 * 32; i += 256) {
            int r = i >> 5, c4 = (i & 31) * 4;
            float4 k4 = *(const float4*)(Kbase + (size_t)(n0 + r) * HD + c4);
            Ks[r * QS_STRIDE + c4 + 0] = k4.x;
            Ks[r * QS_STRIDE + c4 + 1] = k4.y;
            Ks[r * QS_STRIDE + c4 + 2] = k4.z;
            Ks[r * QS_STRIDE + c4 + 3] = k4.w;
            float4 v4 = *(const float4*)(Vbase + (size_t)(n0 + r) * HD + c4);
            *(float4*)(Vs + r * 128 + c4) = v4;
        }
        __syncthreads();

        float s[4][4];
#pragma unroll
        for (int i = 0; i < 4; i++)
#pragma unroll
            for (int j = 0; j < 4; j++) s[i][j] = 0.f;

        for (int d = 0; d < HD; ++d) {
            float qa[4], kb[4];
#pragma unroll
            for (int i = 0; i < 4; i++) qa[i] = Qs[(r0 + i) * QS_STRIDE + d];
#pragma unroll
            for (int j = 0; j < 4; j++) kb[j] = Ks[(cS0 + j) * QS_STRIDE + d];
#pragma unroll
            for (int i = 0; i < 4; i++)
#pragma unroll
                for (int j = 0; j < 4; j++)
                    s[i][j] = fmaf(qa[i], kb[j], s[i][j]);
        }
#pragma unroll
        for (int i = 0; i < 4; i++) {
            const int qi = m0 + r0 + i;
#pragma unroll
            for (int j = 0; j < 4; j++) {
                const int ki = n0 + cS0 + j;
                Ss[(r0 + i) * SS_STRIDE + cS0 + j] =
                    (ki <= qi) ? s[i][j] * SCALE : -1e30f;
            }
        }
        __syncthreads();

        {
            const int sr = tid >> 2;
            const int sl = tid & 3;
            const int cb = sl * 16;
            float mx = -1e30f;
#pragma unroll
            for (int c = 0; c < 16; c++)
                mx = fmaxf(mx, Ss[sr * SS_STRIDE + cb + c]);
            mx = fmaxf(mx, __shfl_xor_sync(0xffffffffu, mx, 1));
            mx = fmaxf(mx, __shfl_xor_sync(0xffffffffu, mx, 2));
            const float mo = m_s[sr];
            mx = fmaxf(mx, mo);
            float l = 0.f;
#pragma unroll
            for (int c = 0; c < 16; c++) {
                const float p = __expf(Ss[sr * SS_STRIDE + cb + c] - mx);
                Ss[sr * SS_STRIDE + cb + c] = p;
                l += p;
            }
            l += __shfl_xor_sync(0xffffffffu, l, 1);
            l += __shfl_xor_sync(0xffffffffu, l, 2);
            if (sl == 0) {
                const float scl = __expf(mo - mx);
                l_s[sr] = l_s[sr] * scl + l;
                m_s[sr] = mx;
                sc_s[sr] = scl;
            }
        }
        __syncthreads();

#pragma unroll
        for (int i = 0; i < 4; i++) {
            const float scl = sc_s[r0 + i];
#pragma unroll
            for (int j = 0; j < 8; j++) acc[i][j] *= scl;
        }
        for (int n = 0; n < 64; ++n) {
            float p[4];
#pragma unroll
            for (int i = 0; i < 4; i++) p[i] = Ss[(r0 + i) * SS_STRIDE + n];
            const float4 v0 = *(const float4*)(Vs + n * 128 + cO0);
            const float4 v1 = *(const float4*)(Vs + n * 128 + cO0 + 4);
#pragma unroll
            for (int i = 0; i < 4; i++) {
                acc[i][0] = fmaf(p[i], v0.x, acc[i][0]);
                acc[i][1] = fmaf(p[i], v0.y, acc[i][1]);
                acc[i][2] = fmaf(p[i], v0.z, acc[i][2]);
                acc[i][3] = fmaf(p[i], v0.w, acc[i][3]);
                acc[i][4] = fmaf(p[i], v1.x, acc[i][4]);
                acc[i][5] = fmaf(p[i], v1.y, acc[i][5]);
                acc[i][6] = fmaf(p[i], v1.z, acc[i][6]);
                acc[i][7] = fmaf(p[i], v1.w, acc[i][7]);
            }
        }
        __syncthreads();
    }

#pragma unroll
    for (int i = 0; i < 4; i++) {
        const float invl = 1.0f / l_s[r0 + i];
        const int srow = m0 + r0 + i;
        float* o = g_ctx + ((size_t)b * SEQ + srow) * (NH * HD) + h * HD + cO0;
        *(float4*)(o)     = make_float4(acc[i][0] * invl, acc[i][1] * invl,
                                        acc[i][2] * invl, acc[i][3] * invl);
        *(float4*)(o + 4) = make_float4(acc[i][4] * invl, acc[i][5] * invl,
                                        acc[i][6] * invl, acc[i][7] * invl);
    }
}

// ---------------------------------------------------------------------------
extern "C" void kernel_launch(void* const* d_in, const int* in_sizes, int n_in,
                              void* d_out, int out_size)
{
    const float* hidden = (const float*)d_in[0];
    const float* cosb   = (const float*)d_in[1];
    const float* sinb   = (const float*)d_in[2];
    const float* w_qkv  = (const float*)d_in[3];
    const float* q_w    = (const float*)d_in[4];
    const float* k_w    = (const float*)d_in[5];
    const float* w_o    = (const float*)d_in[6];
    float* out = (float*)d_out;

    float *qkv_p, *q_p, *k_p, *v_p, *ctx_p;
    unsigned *wqkvt_p, *wot_p;
    cudaGetSymbolAddress((void**)&qkv_p,   g_qkv);
    cudaGetSymbolAddress((void**)&q_p,     g_q);
    cudaGetSymbolAddress((void**)&k_p,     g_k);
    cudaGetSymbolAddress((void**)&v_p,     g_v);
    cudaGetSymbolAddress((void**)&ctx_p,   g_ctx);
    cudaGetSymbolAddress((void**)&wqkvt_p, g_wqkv_t);
    cudaGetSymbolAddress((void**)&wot_p,   g_wo_t);

    const int gemm_smem = 4 * 128 * GS * 4;   // 73728 bytes
    cudaFuncSetAttribute(gemm_nt, cudaFuncAttributeMaxDynamicSharedMemorySize, gemm_smem);
    const int attn_smem = (64 * QS_STRIDE * 2 + 64 * 128 + 64 * SS_STRIDE + 192) * 4;
    cudaFuncSetAttribute(attn_kernel, cudaFuncAttributeMaxDynamicSharedMemorySize, attn_smem);

    // 0) pre-transpose + tf32-convert weights (n-major)
    transpose_tf32<<<dim3(NQKV / 32, HID / 32), dim3(32, 8)>>>(w_qkv, wqkvt_p, HID, NQKV);
    transpose_tf32<<<dim3(HID / 32, (NH * HD) / 32), dim3(32, 8)>>>(w_o, wot_p, NH * HD, HID);

    // 1) QKV projection: M=2048, N=5120, K=2048
    gemm_nt<<<dim3(NQKV / 128, TOK / 128), 256, gemm_smem>>>(hidden, wqkvt_p, qkv_p, TOK, NQKV, HID);

    // 2) RMSNorm + RoPE + split
    norm_rope_kernel<<<dim3(TOK, 40), 128>>>(qkv_p, cosb, sinb, q_w, k_w, q_p, k_p, v_p);

    // 3) causal GQA attention (FFMA flash, known good)
    attn_kernel<<<dim3(SEQ / 64, NH, BATCH), 256, attn_smem>>>(q_p, k_p, v_p);

    // 4) output projection: M=2048, N=2048, K=4096
    gemm_nt<<<dim3(HID / 128, TOK / 128), 256, gemm_smem>>>(ctx_p, wot_p, out, TOK, HID, NH * HD);

    (void)in_sizes; (void)n_in; (void)out_size;
}

// round 6
// speedup vs baseline: 1.9571x; 1.5280x over previous
#include <cuda_runtime.h>
#include <cuda_bf16.h>
#include <math.h>

// Problem constants
#define BATCH 2
#define SEQ   1024
#define HID   2048
#define NH    32
#define NKV   4
#define GRP   8
#define HD    128
#define NQKV  5120
#define TOK   (BATCH*SEQ)
#define SCALE 0.08838834764831845f
#define RMS_EPS 1e-6f

// -------------------- scratch -------------------------------------------
__device__ float    g_qkv[TOK * NQKV];
__device__ float    g_q[BATCH * NH * SEQ * HD];
__device__ float    g_k[BATCH * NKV * SEQ * HD];
__device__ float    g_v[BATCH * NKV * SEQ * HD];
__device__ float    g_ctx[TOK * NH * HD];
__device__ unsigned g_wqkv_t[NQKV * HID];
__device__ unsigned g_wo_t[HID * (NH * HD)];

__device__ __forceinline__ unsigned f2tf32(float x) {
    unsigned y;
    asm("cvt.rna.tf32.f32 %0, %1;" : "=r"(y) : "f"(x));
    return y;
}

__device__ __forceinline__ void mma_tf32(float c[4],
    unsigned a0, unsigned a1, unsigned a2, unsigned a3,
    unsigned b0, unsigned b1)
{
    asm volatile(
        "mma.sync.aligned.m16n8k8.row.col.f32.tf32.tf32.f32 "
        "{%0,%1,%2,%3}, {%4,%5,%6,%7}, {%8,%9}, {%0,%1,%2,%3};"
        : "+f"(c[0]), "+f"(c[1]), "+f"(c[2]), "+f"(c[3])
        : "r"(a0), "r"(a1), "r"(a2), "r"(a3), "r"(b0), "r"(b1));
}

__device__ __forceinline__ void ldsm_x4(unsigned r[4], unsigned addr) {
    asm volatile("ldmatrix.sync.aligned.m8n8.x4.shared.b16 {%0,%1,%2,%3}, [%4];"
                 : "=r"(r[0]), "=r"(r[1]), "=r"(r[2]), "=r"(r[3]) : "r"(addr));
}

// ---------------------------------------------------------------------------
// Transpose + tf32-convert (unchanged from R5)
// ---------------------------------------------------------------------------
__global__ __launch_bounds__(256) void transpose_tf32(
    const float* __restrict__ in, unsigned* __restrict__ out, int K, int N)
{
    __shared__ unsigned t[32][33];
    const int tx = threadIdx.x, ty = threadIdx.y;
    const int n0 = blockIdx.x * 32, k0 = blockIdx.y * 32;
#pragma unroll
    for (int i = 0; i < 4; i++) {
        const int k = k0 + ty + i * 8;
        t[ty + i * 8][tx] = f2tf32(in[(size_t)k * N + n0 + tx]);
    }
    __syncthreads();
#pragma unroll
    for (int i = 0; i < 4; i++) {
        const int n = n0 + ty + i * 8;
        out[(size_t)n * K + k0 + tx] = t[tx][ty + i * 8];
    }
}

// ---------------------------------------------------------------------------
// NT tf32 GEMM (unchanged from R5 — passing)
// ---------------------------------------------------------------------------
#define GS 36
#define TSW (128 * GS)
#define STAGE_B (TSW * 4)

__global__ __launch_bounds__(256) void gemm_nt(
    const float* __restrict__ A, const unsigned* __restrict__ Bt,
    float* __restrict__ C, int M, int N, int K)
{
    extern __shared__ unsigned sh[];
    unsigned* Asm = sh;
    unsigned* Bsm = sh + 2 * TSW;

    const int tid  = threadIdx.x;
    const int lane = tid & 31;
    const int wid  = tid >> 5;
    const int bm = blockIdx.y, bn = blockIdx.x;

    const int wm = (wid & 3) * 32;
    const int wn = (wid >> 2) * 64;
    const int qr = lane >> 2, ql = lane & 3;

    const int srow = tid >> 1, scol = (tid & 1) * 16;

    const float*    Ag = A  + (size_t)(bm * 128 + srow) * K + scol;
    const unsigned* Bg = Bt + (size_t)(bn * 128 + srow) * K + scol;

    const unsigned a_base = (unsigned)__cvta_generic_to_shared(Asm);
    const unsigned b_base = (unsigned)__cvta_generic_to_shared(Bsm);
    unsigned a_off[2];
#pragma unroll
    for (int i = 0; i < 2; i++)
        a_off[i] = ((wm + i * 16 + (lane & 7) + (lane & 8)) * GS +
                    ((lane >> 4) << 2)) * 4;
    unsigned b_off[4];
#pragma unroll
    for (int jp = 0; jp < 4; jp++)
        b_off[jp] = ((wn + jp * 16 + (lane & 7) + ((lane & 16) >> 1)) * GS +
                     (((lane >> 3) & 1) << 2)) * 4;

    float acc[2][8][4];
#pragma unroll
    for (int i = 0; i < 2; i++)
#pragma unroll
        for (int j = 0; j < 8; j++)
#pragma unroll
            for (int c = 0; c < 4; c++) acc[i][j][c] = 0.f;

    const int niter = K >> 5;
    uint4 astg[4], bstg[4];

#pragma unroll
    for (int u = 0; u < 4; u++) {
        float4 av = *(const float4*)(Ag + u * 4);
        astg[u] = make_uint4(f2tf32(av.x), f2tf32(av.y), f2tf32(av.z), f2tf32(av.w));
        bstg[u] = *(const uint4*)(Bg + u * 4);
    }
#pragma unroll
    for (int u = 0; u < 4; u++) {
        *(uint4*)&Asm[srow * GS + scol + u * 4] = astg[u];
        *(uint4*)&Bsm[srow * GS + scol + u * 4] = bstg[u];
    }

    for (int it = 0; it < niter; ++it) {
        __syncthreads();
        const int cur = it & 1;
        const bool more = (it + 1) < niter;
        if (more) {
            const int k0 = (it + 1) << 5;
#pragma unroll
            for (int u = 0; u < 4; u++) {
                float4 av = *(const float4*)(Ag + k0 + u * 4);
                astg[u] = make_uint4(f2tf32(av.x), f2tf32(av.y), f2tf32(av.z), f2tf32(av.w));
                bstg[u] = *(const uint4*)(Bg + k0 + u * 4);
            }
        }

        const unsigned a_st = a_base + cur * STAGE_B;
        const unsigned b_st = b_base + cur * STAGE_B;
#pragma unroll
        for (int kk = 0; kk < 4; kk++) {
            const unsigned koff = kk * 32;
            unsigned a[2][4];
            ldsm_x4(a[0], a_st + a_off[0] + koff);
            ldsm_x4(a[1], a_st + a_off[1] + koff);
#pragma unroll
            for (int jp = 0; jp < 4; jp++) {
                unsigned bfr[4];
                ldsm_x4(bfr, b_st + b_off[jp] + koff);
#pragma unroll
                for (int i = 0; i < 2; i++) {
                    mma_tf32(acc[i][2 * jp],     a[i][0], a[i][1], a[i][2], a[i][3], bfr[0], bfr[1]);
                    mma_tf32(acc[i][2 * jp + 1], a[i][0], a[i][1], a[i][2], a[i][3], bfr[2], bfr[3]);
                }
            }
        }

        if (more) {
            const int nxt = (it + 1) & 1;
            unsigned* Ad = Asm + nxt * TSW;
            unsigned* Bd = Bsm + nxt * TSW;
#pragma unroll
            for (int u = 0; u < 4; u++) {
                *(uint4*)&Ad[srow * GS + scol + u * 4] = astg[u];
                *(uint4*)&Bd[srow * GS + scol + u * 4] = bstg[u];
            }
        }
    }

#pragma unroll
    for (int i = 0; i < 2; i++) {
        const int r0 = bm * 128 + wm + i * 16 + qr;
#pragma unroll
        for (int j = 0; j < 8; j++) {
            const int c = bn * 128 + wn + j * 8 + ql * 2;
            *(float2*)(C + (size_t)r0 * N + c)       = make_float2(acc[i][j][0], acc[i][j][1]);
            *(float2*)(C + (size_t)(r0 + 8) * N + c) = make_float2(acc[i][j][2], acc[i][j][3]);
        }
    }
}

// ---------------------------------------------------------------------------
// RMSNorm + RoPE + split (unchanged)
// ---------------------------------------------------------------------------
__global__ __launch_bounds__(128) void norm_rope_kernel(
    const float* __restrict__ qkv, const float* __restrict__ cosb,
    const float* __restrict__ sinb, const float* __restrict__ qw,
    const float* __restrict__ kw,
    float* __restrict__ Q, float* __restrict__ K, float* __restrict__ V)
{
    const int token = blockIdx.x;
    const int slot  = blockIdx.y;
    const int d     = threadIdx.x;
    const int b = token / SEQ, s = token % SEQ;

    const float x = qkv[(size_t)token * NQKV + slot * HD + d];

    if (slot >= 36) {
        const int kh = slot - 36;
        V[((size_t)(b * NKV + kh) * SEQ + s) * HD + d] = x;
        return;
    }

    __shared__ float xn[HD];
    __shared__ float red[4];

    float ss = x * x;
#pragma unroll
    for (int o = 16; o > 0; o >>= 1) ss += __shfl_xor_sync(0xffffffffu, ss, o);
    if ((d & 31) == 0) red[d >> 5] = ss;
    __syncthreads();
    const float tot = red[0] + red[1] + red[2] + red[3];
    const float inv = rsqrtf(tot * (1.0f / HD) + RMS_EPS);

    const float* w = (slot < 32) ? qw : kw;
    const float v = x * inv * w[d];
    xn[d] = v;
    __syncthreads();

    const float rot = (d < 64) ? -xn[d + 64] : xn[d - 64];
    const float c  = cosb[(size_t)s * HD + d];
    const float sn = sinb[(size_t)s * HD + d];
    const float out = v * c + rot * sn;

    if (slot < 32)
        Q[((size_t)(b * NH + slot) * SEQ + s) * HD + d] = out;
    else
        K[((size_t)(b * NKV + (slot - 32)) * SEQ + s) * HD + d] = out;
}

// ---------------------------------------------------------------------------
// Tensor-core causal GQA flash attention v2.
// 32 q x 64 kv tiles, 256 threads (8 warps), ~98.7KB smem -> 2 CTAs/SM.
// Plain tf32 for QK^T and P*V. LDSM fragments for Q/K/P; scalar B-frags for V.
// Warp grid: 2(m) x 4(n). QK warp tile 16x16; PV warp tile 16x32.
// ---------------------------------------------------------------------------
#define AT_CH (32 * 36)   // Q/P chunk words (32 rows x 36 stride)
#define KT_CH (64 * 36)   // K chunk words
#define VST   132         // V smem row stride (words)

__global__ __launch_bounds__(256) void attn_tc32(
    const float* __restrict__ Q, const float* __restrict__ K,
    const float* __restrict__ V)
{
    extern __shared__ unsigned ash[];
    unsigned* Qs = ash;                  // [4][32][36] tf32, pre-scaled
    unsigned* Ks = Qs + 4 * AT_CH;       // [4][64][36] tf32
    unsigned* Vs = Ks + 4 * KT_CH;       // [64][132]   tf32
    unsigned* Ps = Vs + 64 * VST;        // [2][32][36] scores fp32 -> probs tf32
    float*   m_s = (float*)(Ps + 2 * AT_CH);
    float*   l_s = m_s + 32;
    float*  sc_s = l_s + 32;

    const int mt = (gridDim.x - 1) - blockIdx.x;    // heavy tiles first
    const int h = blockIdx.y, b = blockIdx.z;
    const int kh = h / GRP;
    const int tid = threadIdx.x, lane = tid & 31, wid = tid >> 5;
    const int qr = lane >> 2, ql = lane & 3;
    const int wm2 = (wid & 1) * 16;    // q-row band
    const int wn2 = (wid >> 1) * 16;   // kv band (QK)
    const int wn3 = (wid >> 1) * 32;   // d band (PV)
    const int m0 = mt * 32;

    const float* Qb = Q + ((size_t)(b * NH + h) * SEQ + m0) * HD;
    const float* Kb = K + ((size_t)(b * NKV + kh) * SEQ) * HD;
    const float* Vb = V + ((size_t)(b * NKV + kh) * SEQ) * HD;

    // stage Q (32x128), pre-scaled, tf32, chunked [c][r][36]
    for (int i = tid; i < 32 * 32; i += 256) {
        const int r = i >> 5, c4 = (i & 31) * 4;
        float4 q4 = *(const float4*)(Qb + (size_t)r * HD + c4);
        unsigned* dst = Qs + (c4 >> 5) * AT_CH + r * 36 + (c4 & 31);
        dst[0] = f2tf32(q4.x * SCALE); dst[1] = f2tf32(q4.y * SCALE);
        dst[2] = f2tf32(q4.z * SCALE); dst[3] = f2tf32(q4.w * SCALE);
    }
    if (tid < 32) { m_s[tid] = -1e30f; l_s[tid] = 0.f; }

    const unsigned qs_base = (unsigned)__cvta_generic_to_shared(Qs);
    const unsigned ks_base = (unsigned)__cvta_generic_to_shared(Ks);
    const unsigned ps_base = (unsigned)__cvta_generic_to_shared(Ps);
    const unsigned a_off = ((wm2 + (lane & 7) + (lane & 8)) * 36 +
                            ((lane >> 4) << 2)) * 4;
    const unsigned bk_off = ((wn2 + (lane & 7) + ((lane & 16) >> 1)) * 36 +
                             (((lane >> 3) & 1) << 2)) * 4;

    const int row0 = wm2 + qr, row1 = row0 + 8;

    float oacc[4][4];
#pragma unroll
    for (int j = 0; j < 4; j++)
#pragma unroll
        for (int c = 0; c < 4; c++) oacc[j][c] = 0.f;

    const int ntiles = (m0 + 95) >> 6;
    for (int t = 0; t < ntiles; ++t) {
        const int n0 = t * 64;
        // stage K (chunked) + V (flat), tf32
        for (int i = tid; i < 64 * 32; i += 256) {
            const int r = i >> 5, c4 = (i & 31) * 4;
            float4 k4 = *(const float4*)(Kb + (size_t)(n0 + r) * HD + c4);
            unsigned* kd = Ks + (c4 >> 5) * KT_CH + r * 36 + (c4 & 31);
            kd[0] = f2tf32(k4.x); kd[1] = f2tf32(k4.y);
            kd[2] = f2tf32(k4.z); kd[3] = f2tf32(k4.w);
            float4 v4 = *(const float4*)(Vb + (size_t)(n0 + r) * HD + c4);
            unsigned* vd = Vs + r * VST + c4;
            vd[0] = f2tf32(v4.x); vd[1] = f2tf32(v4.y);
            vd[2] = f2tf32(v4.z); vd[3] = f2tf32(v4.w);
        }
        __syncthreads();

        // QK^T: 16 x 16 per warp, k over 128
        float sacc[2][4];
#pragma unroll
        for (int j = 0; j < 2; j++)
#pragma unroll
            for (int c = 0; c < 4; c++) sacc[j][c] = 0.f;

#pragma unroll
        for (int k8 = 0; k8 < 16; k8++) {
            const int cch = k8 >> 2, kk = k8 & 3;
            unsigned afr[4], bfr[4];
            ldsm_x4(afr, qs_base + cch * (AT_CH * 4) + a_off + kk * 32);
            ldsm_x4(bfr, ks_base + cch * (KT_CH * 4) + bk_off + kk * 32);
            mma_tf32(sacc[0], afr[0], afr[1], afr[2], afr[3], bfr[0], bfr[1]);
            mma_tf32(sacc[1], afr[0], afr[1], afr[2], afr[3], bfr[2], bfr[3]);
        }

        // writeback scores (fp32 bits) into Ps, masking only on diagonal tile
        const bool last = (t == ntiles - 1);
#pragma unroll
        for (int j = 0; j < 2; j++) {
            const int cg = wn2 + j * 8 + 2 * ql;
            float* p0 = (float*)(Ps + (cg >> 5) * AT_CH + row0 * 36 + (cg & 31));
            float* p1 = (float*)(Ps + (cg >> 5) * AT_CH + row1 * 36 + (cg & 31));
            if (last) {
                const int kg = n0 + cg, q0g = m0 + row0, q1g = m0 + row1;
                p0[0] = (kg     <= q0g) ? sacc[j][0] : -1e30f;
                p0[1] = (kg + 1 <= q0g) ? sacc[j][1] : -1e30f;
                p1[0] = (kg     <= q1g) ? sacc[j][2] : -1e30f;
                p1[1] = (kg + 1 <= q1g) ? sacc[j][3] : -1e30f;
            } else {
                p0[0] = sacc[j][0]; p0[1] = sacc[j][1];
                p1[0] = sacc[j][2]; p1[1] = sacc[j][3];
            }
        }
        __syncthreads();

        // online softmax: 8 threads/row (32 rows), probs written back as tf32
        {
            const int sr = tid >> 3, sl = tid & 7;
            unsigned* base = Ps + (sl >> 2) * AT_CH + sr * 36 + ((sl * 8) & 31);
            float v[8];
            float mx = -1e30f;
#pragma unroll
            for (int c = 0; c < 8; c++) {
                v[c] = __uint_as_float(base[c]);
                mx = fmaxf(mx, v[c]);
            }
            mx = fmaxf(mx, __shfl_xor_sync(0xffffffffu, mx, 1));
            mx = fmaxf(mx, __shfl_xor_sync(0xffffffffu, mx, 2));
            mx = fmaxf(mx, __shfl_xor_sync(0xffffffffu, mx, 4));
            const float mo = m_s[sr];
            mx = fmaxf(mx, mo);
            float l = 0.f;
#pragma unroll
            for (int c = 0; c < 8; c++) {
                const float p = __expf(v[c] - mx);
                base[c] = f2tf32(p);
                l += p;
            }
            l += __shfl_xor_sync(0xffffffffu, l, 1);
            l += __shfl_xor_sync(0xffffffffu, l, 2);
            l += __shfl_xor_sync(0xffffffffu, l, 4);
            if (sl == 0) {
                const float scl = __expf(mo - mx);
                l_s[sr] = l_s[sr] * scl + l;
                m_s[sr] = mx;
                sc_s[sr] = scl;
            }
        }
        __syncthreads();

        // rescale old acc + P*V
        {
            const float s0 = sc_s[row0], s1 = sc_s[row1];
#pragma unroll
            for (int j = 0; j < 4; j++) {
                oacc[j][0] *= s0; oacc[j][1] *= s0;
                oacc[j][2] *= s1; oacc[j][3] *= s1;
            }
        }
#pragma unroll
        for (int kb = 0; kb < 8; kb++) {
            const int cch = kb >> 2, kk = kb & 3;
            unsigned afr[4];
            ldsm_x4(afr, ps_base + cch * (AT_CH * 4) + a_off + kk * 32);
            const int kidx = kb * 8 + ql;
#pragma unroll
            for (int j = 0; j < 4; j++) {
                const int n = wn3 + j * 8 + qr;
                unsigned b0 = Vs[kidx * VST + n];
                unsigned b1 = Vs[(kidx + 4) * VST + n];
                mma_tf32(oacc[j], afr[0], afr[1], afr[2], afr[3], b0, b1);
            }
        }
        __syncthreads();
    }

    // epilogue: normalize, write ctx[b, s, h*HD + d]
    const float il0 = 1.0f / l_s[row0];
    const float il1 = 1.0f / l_s[row1];
#pragma unroll
    for (int j = 0; j < 4; j++) {
        const int col = wn3 + j * 8 + 2 * ql;
        float* o0 = g_ctx + ((size_t)b * SEQ + m0 + row0) * (NH * HD) + h * HD + col;
        float* o1 = g_ctx + ((size_t)b * SEQ + m0 + row1) * (NH * HD) + h * HD + col;
        *(float2*)o0 = make_float2(oacc[j][0] * il0, oacc[j][1] * il0);
        *(float2*)o1 = make_float2(oacc[j][2] * il1, oacc[j][3] * il1);
    }
}

// ---------------------------------------------------------------------------
extern "C" void kernel_launch(void* const* d_in, const int* in_sizes, int n_in,
                              void* d_out, int out_size)
{
    const float* hidden = (const float*)d_in[0];
    const float* cosb   = (const float*)d_in[1];
    const float* sinb   = (const float*)d_in[2];
    const float* w_qkv  = (const float*)d_in[3];
    const float* q_w    = (const float*)d_in[4];
    const float* k_w    = (const float*)d_in[5];
    const float* w_o    = (const float*)d_in[6];
    float* out = (float*)d_out;

    float *qkv_p, *q_p, *k_p, *v_p, *ctx_p;
    unsigned *wqkvt_p, *wot_p;
    cudaGetSymbolAddress((void**)&qkv_p,   g_qkv);
    cudaGetSymbolAddress((void**)&q_p,     g_q);
    cudaGetSymbolAddress((void**)&k_p,     g_k);
    cudaGetSymbolAddress((void**)&v_p,     g_v);
    cudaGetSymbolAddress((void**)&ctx_p,   g_ctx);
    cudaGetSymbolAddress((void**)&wqkvt_p, g_wqkv_t);
    cudaGetSymbolAddress((void**)&wot_p,   g_wo_t);

    const int gemm_smem = 4 * 128 * GS * 4;
    cudaFuncSetAttribute(gemm_nt, cudaFuncAttributeMaxDynamicSharedMemorySize, gemm_smem);
    const int attn_smem = (4 * AT_CH + 4 * KT_CH + 64 * VST + 2 * AT_CH + 96) * 4;
    cudaFuncSetAttribute(attn_tc32, cudaFuncAttributeMaxDynamicSharedMemorySize, attn_smem);

    // 0) pre-transpose + tf32-convert weights
    transpose_tf32<<<dim3(NQKV / 32, HID / 32), dim3(32, 8)>>>(w_qkv, wqkvt_p, HID, NQKV);
    transpose_tf32<<<dim3(HID / 32, (NH * HD) / 32), dim3(32, 8)>>>(w_o, wot_p, NH * HD, HID);

    // 1) QKV projection
    gemm_nt<<<dim3(NQKV / 128, TOK / 128), 256, gemm_smem>>>(hidden, wqkvt_p, qkv_p, TOK, NQKV, HID);

    // 2) RMSNorm + RoPE + split
    norm_rope_kernel<<<dim3(TOK, 40), 128>>>(qkv_p, cosb, sinb, q_w, k_w, q_p, k_p, v_p);

    // 3) causal GQA attention (tensor cores, 32x64 tiles)
    attn_tc32<<<dim3(SEQ / 32, NH, BATCH), 256, attn_smem>>>(q_p, k_p, v_p);

    // 4) output projection
    gemm_nt<<<dim3(HID / 128, TOK / 128), 256, gemm_smem>>>(ctx_p, wot_p, out, TOK, HID, NH * HD);

    (void)in_sizes; (void)n_in; (void)out_size;
}

// round 7
// speedup vs baseline: 2.0576x; 1.0513x over previous
#include <cuda_runtime.h>
#include <cuda_bf16.h>
#include <math.h>

// Problem constants
#define BATCH 2
#define SEQ   1024
#define HID   2048
#define NH    32
#define NKV   4
#define GRP   8
#define HD    128
#define NQKV  5120
#define TOK   (BATCH*SEQ)
#define SCALE 0.08838834764831845f
#define RMS_EPS 1e-6f

// -------------------- scratch -------------------------------------------
__device__ float    g_qkv[TOK * NQKV];
__device__ unsigned g_qt[BATCH * NH * SEQ * HD];    // tf32, pre-scaled by SCALE
__device__ unsigned g_kt[BATCH * NKV * SEQ * HD];   // tf32
__device__ unsigned g_vt[BATCH * NKV * SEQ * HD];   // tf32
__device__ float    g_ctx[TOK * NH * HD];
__device__ unsigned g_wqkv_t[NQKV * HID];
__device__ unsigned g_wo_t[HID * (NH * HD)];

__device__ __forceinline__ unsigned f2tf32(float x) {
    unsigned y;
    asm("cvt.rna.tf32.f32 %0, %1;" : "=r"(y) : "f"(x));
    return y;
}

__device__ __forceinline__ void mma_tf32(float c[4],
    unsigned a0, unsigned a1, unsigned a2, unsigned a3,
    unsigned b0, unsigned b1)
{
    asm volatile(
        "mma.sync.aligned.m16n8k8.row.col.f32.tf32.tf32.f32 "
        "{%0,%1,%2,%3}, {%4,%5,%6,%7}, {%8,%9}, {%0,%1,%2,%3};"
        : "+f"(c[0]), "+f"(c[1]), "+f"(c[2]), "+f"(c[3])
        : "r"(a0), "r"(a1), "r"(a2), "r"(a3), "r"(b0), "r"(b1));
}

__device__ __forceinline__ void ldsm_x4(unsigned r[4], unsigned addr) {
    asm volatile("ldmatrix.sync.aligned.m8n8.x4.shared.b16 {%0,%1,%2,%3}, [%4];"
                 : "=r"(r[0]), "=r"(r[1]), "=r"(r[2]), "=r"(r[3]) : "r"(addr));
}

#define CP_ASYNC16(dst_u32, src_ptr) \
    asm volatile("cp.async.cg.shared.global [%0], [%1], 16;" :: "r"(dst_u32), "l"(src_ptr))
#define CP_COMMIT() asm volatile("cp.async.commit_group;")
#define CP_WAIT0()  asm volatile("cp.async.wait_group 0;")
#define CP_WAIT1()  asm volatile("cp.async.wait_group 1;")

// ---------------------------------------------------------------------------
// Transpose + tf32-convert (unchanged)
// ---------------------------------------------------------------------------
__global__ __launch_bounds__(256) void transpose_tf32(
    const float* __restrict__ in, unsigned* __restrict__ out, int K, int N)
{
    __shared__ unsigned t[32][33];
    const int tx = threadIdx.x, ty = threadIdx.y;
    const int n0 = blockIdx.x * 32, k0 = blockIdx.y * 32;
#pragma unroll
    for (int i = 0; i < 4; i++) {
        const int k = k0 + ty + i * 8;
        t[ty + i * 8][tx] = f2tf32(in[(size_t)k * N + n0 + tx]);
    }
    __syncthreads();
#pragma unroll
    for (int i = 0; i < 4; i++) {
        const int n = n0 + ty + i * 8;
        out[(size_t)n * K + k0 + tx] = t[tx][ty + i * 8];
    }
}

// ---------------------------------------------------------------------------
// NT tf32 GEMM (unchanged from R5 — passing)
// ---------------------------------------------------------------------------
#define GS 36
#define TSW (128 * GS)
#define STAGE_B (TSW * 4)

__global__ __launch_bounds__(256) void gemm_nt(
    const float* __restrict__ A, const unsigned* __restrict__ Bt,
    float* __restrict__ C, int M, int N, int K)
{
    extern __shared__ unsigned sh[];
    unsigned* Asm = sh;
    unsigned* Bsm = sh + 2 * TSW;

    const int tid  = threadIdx.x;
    const int lane = tid & 31;
    const int wid  = tid >> 5;
    const int bm = blockIdx.y, bn = blockIdx.x;

    const int wm = (wid & 3) * 32;
    const int wn = (wid >> 2) * 64;
    const int qr = lane >> 2, ql = lane & 3;

    const int srow = tid >> 1, scol = (tid & 1) * 16;

    const float*    Ag = A  + (size_t)(bm * 128 + srow) * K + scol;
    const unsigned* Bg = Bt + (size_t)(bn * 128 + srow) * K + scol;

    const unsigned a_base = (unsigned)__cvta_generic_to_shared(Asm);
    const unsigned b_base = (unsigned)__cvta_generic_to_shared(Bsm);
    unsigned a_off[2];
#pragma unroll
    for (int i = 0; i < 2; i++)
        a_off[i] = ((wm + i * 16 + (lane & 7) + (lane & 8)) * GS +
                    ((lane >> 4) << 2)) * 4;
    unsigned b_off[4];
#pragma unroll
    for (int jp = 0; jp < 4; jp++)
        b_off[jp] = ((wn + jp * 16 + (lane & 7) + ((lane & 16) >> 1)) * GS +
                     (((lane >> 3) & 1) << 2)) * 4;

    float acc[2][8][4];
#pragma unroll
    for (int i = 0; i < 2; i++)
#pragma unroll
        for (int j = 0; j < 8; j++)
#pragma unroll
            for (int c = 0; c < 4; c++) acc[i][j][c] = 0.f;

    const int niter = K >> 5;
    uint4 astg[4], bstg[4];

#pragma unroll
    for (int u = 0; u < 4; u++) {
        float4 av = *(const float4*)(Ag + u * 4);
        astg[u] = make_uint4(f2tf32(av.x), f2tf32(av.y), f2tf32(av.z), f2tf32(av.w));
        bstg[u] = *(const uint4*)(Bg + u * 4);
    }
#pragma unroll
    for (int u = 0; u < 4; u++) {
        *(uint4*)&Asm[srow * GS + scol + u * 4] = astg[u];
        *(uint4*)&Bsm[srow * GS + scol + u * 4] = bstg[u];
    }

    for (int it = 0; it < niter; ++it) {
        __syncthreads();
        const int cur = it & 1;
        const bool more = (it + 1) < niter;
        if (more) {
            const int k0 = (it + 1) << 5;
#pragma unroll
            for (int u = 0; u < 4; u++) {
                float4 av = *(const float4*)(Ag + k0 + u * 4);
                astg[u] = make_uint4(f2tf32(av.x), f2tf32(av.y), f2tf32(av.z), f2tf32(av.w));
                bstg[u] = *(const uint4*)(Bg + k0 + u * 4);
            }
        }

        const unsigned a_st = a_base + cur * STAGE_B;
        const unsigned b_st = b_base + cur * STAGE_B;
#pragma unroll
        for (int kk = 0; kk < 4; kk++) {
            const unsigned koff = kk * 32;
            unsigned a[2][4];
            ldsm_x4(a[0], a_st + a_off[0] + koff);
            ldsm_x4(a[1], a_st + a_off[1] + koff);
#pragma unroll
            for (int jp = 0; jp < 4; jp++) {
                unsigned bfr[4];
                ldsm_x4(bfr, b_st + b_off[jp] + koff);
#pragma unroll
                for (int i = 0; i < 2; i++) {
                    mma_tf32(acc[i][2 * jp],     a[i][0], a[i][1], a[i][2], a[i][3], bfr[0], bfr[1]);
                    mma_tf32(acc[i][2 * jp + 1], a[i][0], a[i][1], a[i][2], a[i][3], bfr[2], bfr[3]);
                }
            }
        }

        if (more) {
            const int nxt = (it + 1) & 1;
            unsigned* Ad = Asm + nxt * TSW;
            unsigned* Bd = Bsm + nxt * TSW;
#pragma unroll
            for (int u = 0; u < 4; u++) {
                *(uint4*)&Ad[srow * GS + scol + u * 4] = astg[u];
                *(uint4*)&Bd[srow * GS + scol + u * 4] = bstg[u];
            }
        }
    }

#pragma unroll
    for (int i = 0; i < 2; i++) {
        const int r0 = bm * 128 + wm + i * 16 + qr;
#pragma unroll
        for (int j = 0; j < 8; j++) {
            const int c = bn * 128 + wn + j * 8 + ql * 2;
            *(float2*)(C + (size_t)r0 * N + c)       = make_float2(acc[i][j][0], acc[i][j][1]);
            *(float2*)(C + (size_t)(r0 + 8) * N + c) = make_float2(acc[i][j][2], acc[i][j][3]);
        }
    }
}

// ---------------------------------------------------------------------------
// RMSNorm + RoPE + split — now emits tf32 (u32); Q pre-scaled by SCALE.
// Numerically identical to converting in the attention kernel (R6).
// ---------------------------------------------------------------------------
__global__ __launch_bounds__(128) void norm_rope_kernel(
    const float* __restrict__ qkv, const float* __restrict__ cosb,
    const float* __restrict__ sinb, const float* __restrict__ qw,
    const float* __restrict__ kw,
    unsigned* __restrict__ Q, unsigned* __restrict__ K, unsigned* __restrict__ V)
{
    const int token = blockIdx.x;
    const int slot  = blockIdx.y;
    const int d     = threadIdx.x;
    const int b = token / SEQ, s = token % SEQ;

    const float x = qkv[(size_t)token * NQKV + slot * HD + d];

    if (slot >= 36) {
        const int kh = slot - 36;
        V[((size_t)(b * NKV + kh) * SEQ + s) * HD + d] = f2tf32(x);
        return;
    }

    __shared__ float xn[HD];
    __shared__ float red[4];

    float ss = x * x;
#pragma unroll
    for (int o = 16; o > 0; o >>= 1) ss += __shfl_xor_sync(0xffffffffu, ss, o);
    if ((d & 31) == 0) red[d >> 5] = ss;
    __syncthreads();
    const float tot = red[0] + red[1] + red[2] + red[3];
    const float inv = rsqrtf(tot * (1.0f / HD) + RMS_EPS);

    const float* w = (slot < 32) ? qw : kw;
    const float v = x * inv * w[d];
    xn[d] = v;
    __syncthreads();

    const float rot = (d < 64) ? -xn[d + 64] : xn[d - 64];
    const float c  = cosb[(size_t)s * HD + d];
    const float sn = sinb[(size_t)s * HD + d];
    const float out = v * c + rot * sn;

    if (slot < 32)
        Q[((size_t)(b * NH + slot) * SEQ + s) * HD + d] = f2tf32(out * SCALE);
    else
        K[((size_t)(b * NKV + (slot - 32)) * SEQ + s) * HD + d] = f2tf32(out);
}

// ---------------------------------------------------------------------------
// Tensor-core causal GQA flash attention v3.
// CTA = 4 q-heads x 32 positions = 128 q-rows, kv tile 32, 512 threads.
// KV shared across the 4 heads (GQA); cp.async 2-stage KV pipeline.
// Warp grid: QK 8m x 2n (warp 16x16); PV 8m x 2n (warp 16x64).
// Smem ~164KB -> 1 CTA/SM.
// ---------------------------------------------------------------------------
#define CHQ   (128 * 36)            // Q/P chunk words (128 rows x 36)
#define KCH   (32 * 36)             // K chunk words per d-chunk
#define KSTG  (4 * KCH)             // K stage words (4 chunks)
#define VROW  132
#define VSTG  (32 * VROW)           // V stage words
#define QW    (4 * CHQ)             // Q total words

__global__ __launch_bounds__(512) void attn_tc3(
    const unsigned* __restrict__ Qt, const unsigned* __restrict__ Kt,
    const unsigned* __restrict__ Vt)
{
    extern __shared__ unsigned ash[];
    unsigned* Qs = ash;                   // [4][128][36]
    unsigned* Ks = Qs + QW;               // [2][4][32][36]
    unsigned* Vs = Ks + 2 * KSTG;         // [2][32][132]
    unsigned* Ps = Vs + 2 * VSTG;         // [128][36] scores fp32 -> probs tf32
    float*   m_s = (float*)(Ps + CHQ);    // 128
    float*   l_s = m_s + 128;
    float*  sc_s = l_s + 128;

    const int mt = 31 - blockIdx.x;       // heavy tiles first
    const int hg = blockIdx.y;            // 0..7
    const int b  = blockIdx.z;
    const int kh = hg >> 1;
    const int hbase = kh * GRP + (hg & 1) * 4;
    const int m0 = mt * 32;

    const int tid = threadIdx.x, lane = tid & 31, wid = tid >> 5;
    const int qr = lane >> 2, ql = lane & 3;
    const int wm  = (wid & 7) * 16;       // q-row band
    const int wn  = (wid >> 3) * 16;      // kv band (QK)
    const int wn3 = (wid >> 3) * 64;      // d band (PV)

    const unsigned* Kb = Kt + ((size_t)(b * NKV + kh) * SEQ) * HD;
    const unsigned* Vb = Vt + ((size_t)(b * NKV + kh) * SEQ) * HD;

    const unsigned smem_b = (unsigned)__cvta_generic_to_shared(ash);
    const unsigned qs_base = smem_b;
    const unsigned ks_b    = smem_b + QW * 4;
    const unsigned vs_b    = ks_b + 2 * KSTG * 4;
    const unsigned ps_base = vs_b + 2 * VSTG * 4;

    const int ntiles = mt + 1;

    // ---- KV staging via cp.async: 32 rows x 32 col-groups per operand ----
    // thread covers i and i+512 of 1024 chunks each for K and V
    auto issue_kv = [&](int t) {
        const int st = t & 1;
        const int n0 = t * 32;
#pragma unroll
        for (int u = 0; u < 2; u++) {
            const int i = tid + u * 512;
            const int r = i >> 5, cgrp = i & 31;
            const int cw = cgrp * 4;                     // word col
            const unsigned kdst = ks_b + (st * KSTG + (cgrp >> 3) * KCH +
                                          r * 36 + (cgrp & 7) * 4) * 4;
            CP_ASYNC16(kdst, Kb + (size_t)(n0 + r) * HD + cw);
            const unsigned vdst = vs_b + (st * VSTG + r * VROW + cw) * 4;
            CP_ASYNC16(vdst, Vb + (size_t)(n0 + r) * HD + cw);
        }
        CP_COMMIT();
    };

    // prologue: kick off KV(0), KV(1)
    issue_kv(0);
    if (ntiles > 1) issue_kv(1);

    // stage Q: 128 rows (4 heads x 32 pos) x 128 d, chunked
    for (int i = tid; i < 128 * 32; i += 512) {
        const int r = i >> 5, cw = (i & 31) * 4;
        const int hl = r >> 5, pos = r & 31;
        const uint4 q4 = *(const uint4*)(Qt +
            ((size_t)(b * NH + hbase + hl) * SEQ + m0 + pos) * HD + cw);
        *(uint4*)&Qs[(cw >> 5) * CHQ + r * 36 + (cw & 31)] = q4;
    }
    if (tid < 128) { m_s[tid] = -1e30f; l_s[tid] = 0.f; }

    // fragment offsets (byte), R5-verified formulas
    const unsigned a_off = ((wm + (lane & 7) + (lane & 8)) * 36 +
                            ((lane >> 4) << 2)) * 4;
    const unsigned bk_off = ((wn + (lane & 7) + ((lane & 16) >> 1)) * 36 +
                             (((lane >> 3) & 1) << 2)) * 4;

    const int row0 = wm + qr, row1 = row0 + 8;
    const int hloc = row0 >> 5;                 // head within group (same for row1)
    float* Psf = (float*)Ps;

    float oacc[8][4];
#pragma unroll
    for (int j = 0; j < 8; j++)
#pragma unroll
        for (int c = 0; c < 4; c++) oacc[j][c] = 0.f;

    for (int t = 0; t < ntiles; ++t) {
        const int st = t & 1;
        const int n0 = t * 32;
        if (t + 1 < ntiles) { CP_WAIT1(); } else { CP_WAIT0(); }
        __syncthreads();   // KV(t) visible; prev PV done (stage overwrite safe)

        // ---- QK^T 128x32, warp tile 16x16 ----
        float sacc[2][4];
#pragma unroll
        for (int j = 0; j < 2; j++)
#pragma unroll
            for (int c = 0; c < 4; c++) sacc[j][c] = 0.f;

        const unsigned k_stage = ks_b + st * (KSTG * 4);
#pragma unroll
        for (int k8 = 0; k8 < 16; k8++) {
            const int cch = k8 >> 2, kk = k8 & 3;
            unsigned afr[4], bfr[4];
            ldsm_x4(afr, qs_base + cch * (CHQ * 4) + a_off + kk * 32);
            ldsm_x4(bfr, k_stage + cch * (KCH * 4) + bk_off + kk * 32);
            mma_tf32(sacc[0], afr[0], afr[1], afr[2], afr[3], bfr[0], bfr[1]);
            mma_tf32(sacc[1], afr[0], afr[1], afr[2], afr[3], bfr[2], bfr[3]);
        }

        // ---- masked score writeback ----
        const bool diag = (t == ntiles - 1);
#pragma unroll
        for (int j = 0; j < 2; j++) {
            const int cg = wn + j * 8 + 2 * ql;
            float* p0 = Psf + row0 * 36 + cg;
            float* p1 = Psf + row1 * 36 + cg;
            if (diag) {
                const int p0pos = row0 & 31, p1pos = row1 & 31;
                p0[0] = (cg     <= p0pos) ? sacc[j][0] : -1e30f;
                p0[1] = (cg + 1 <= p0pos) ? sacc[j][1] : -1e30f;
                p1[0] = (cg     <= p1pos) ? sacc[j][2] : -1e30f;
                p1[1] = (cg + 1 <= p1pos) ? sacc[j][3] : -1e30f;
            } else {
                p0[0] = sacc[j][0]; p0[1] = sacc[j][1];
                p1[0] = sacc[j][2]; p1[1] = sacc[j][3];
            }
        }
        __syncthreads();

        // ---- online softmax: 4 threads/row over 32 cols ----
        {
            const int sr = tid >> 2, sl = tid & 3;
            float* base = Psf + sr * 36 + sl * 8;
            float v[8];
            float mx = -1e30f;
#pragma unroll
            for (int c = 0; c < 8; c++) { v[c] = base[c]; mx = fmaxf(mx, v[c]); }
            mx = fmaxf(mx, __shfl_xor_sync(0xffffffffu, mx, 1));
            mx = fmaxf(mx, __shfl_xor_sync(0xffffffffu, mx, 2));
            const float mo = m_s[sr];
            mx = fmaxf(mx, mo);
            float l = 0.f;
#pragma unroll
            for (int c = 0; c < 8; c++) {
                const float p = __expf(v[c] - mx);
                ((unsigned*)base)[c] = f2tf32(p);
                l += p;
            }
            l += __shfl_xor_sync(0xffffffffu, l, 1);
            l += __shfl_xor_sync(0xffffffffu, l, 2);
            if (sl == 0) {
                const float scl = __expf(mo - mx);
                l_s[sr] = l_s[sr] * scl + l;
                m_s[sr] = mx;
                sc_s[sr] = scl;
            }
        }
        __syncthreads();

        // ---- rescale + P*V (128x128 out, warp tile 16x64) ----
        {
            const float s0 = sc_s[row0], s1 = sc_s[row1];
#pragma unroll
            for (int j = 0; j < 8; j++) {
                oacc[j][0] *= s0; oacc[j][1] *= s0;
                oacc[j][2] *= s1; oacc[j][3] *= s1;
            }
        }
        const unsigned* Vst = Vs + st * VSTG;
#pragma unroll
        for (int k8 = 0; k8 < 4; k8++) {
            unsigned afr[4];
            ldsm_x4(afr, ps_base + a_off + k8 * 32);
            const int kidx = k8 * 8 + ql;
#pragma unroll
            for (int j = 0; j < 8; j++) {
                const int n = wn3 + j * 8 + qr;
                const unsigned b0 = Vst[kidx * VROW + n];
                const unsigned b1 = Vst[(kidx + 4) * VROW + n];
                mma_tf32(oacc[j], afr[0], afr[1], afr[2], afr[3], b0, b1);
            }
        }
        __syncthreads();   // stage st fully consumed

        if (t + 2 < ntiles) issue_kv(t + 2);
    }

    // ---- epilogue: normalize and write ctx[b, pos, h*HD + d] ----
    const float il0 = 1.0f / l_s[row0];
    const float il1 = 1.0f / l_s[row1];
    const int h = hbase + hloc;
    const int pos0 = m0 + (row0 & 31), pos1 = m0 + (row1 & 31);
#pragma unroll
    for (int j = 0; j < 8; j++) {
        const int col = wn3 + j * 8 + 2 * ql;
        float* o0 = g_ctx + ((size_t)b * SEQ + pos0) * (NH * HD) + h * HD + col;
        float* o1 = g_ctx + ((size_t)b * SEQ + pos1) * (NH * HD) + h * HD + col;
        *(float2*)o0 = make_float2(oacc[j][0] * il0, oacc[j][1] * il0);
        *(float2*)o1 = make_float2(oacc[j][2] * il1, oacc[j][3] * il1);
    }
}

// ---------------------------------------------------------------------------
extern "C" void kernel_launch(void* const* d_in, const int* in_sizes, int n_in,
                              void* d_out, int out_size)
{
    const float* hidden = (const float*)d_in[0];
    const float* cosb   = (const float*)d_in[1];
    const float* sinb   = (const float*)d_in[2];
    const float* w_qkv  = (const float*)d_in[3];
    const float* q_w    = (const float*)d_in[4];
    const float* k_w    = (const float*)d_in[5];
    const float* w_o    = (const float*)d_in[6];
    float* out = (float*)d_out;

    float *qkv_p, *ctx_p;
    unsigned *qt_p, *kt_p, *vt_p, *wqkvt_p, *wot_p;
    cudaGetSymbolAddress((void**)&qkv_p,   g_qkv);
    cudaGetSymbolAddress((void**)&qt_p,    g_qt);
    cudaGetSymbolAddress((void**)&kt_p,    g_kt);
    cudaGetSymbolAddress((void**)&vt_p,    g_vt);
    cudaGetSymbolAddress((void**)&ctx_p,   g_ctx);
    cudaGetSymbolAddress((void**)&wqkvt_p, g_wqkv_t);
    cudaGetSymbolAddress((void**)&wot_p,   g_wo_t);

    const int gemm_smem = 4 * 128 * GS * 4;
    cudaFuncSetAttribute(gemm_nt, cudaFuncAttributeMaxDynamicSharedMemorySize, gemm_smem);
    const int attn_smem = (QW + 2 * KSTG + 2 * VSTG + CHQ + 3 * 128) * 4;  // ~164KB
    cudaFuncSetAttribute(attn_tc3, cudaFuncAttributeMaxDynamicSharedMemorySize, attn_smem);

    // 0) pre-transpose + tf32-convert weights
    transpose_tf32<<<dim3(NQKV / 32, HID / 32), dim3(32, 8)>>>(w_qkv, wqkvt_p, HID, NQKV);
    transpose_tf32<<<dim3(HID / 32, (NH * HD) / 32), dim3(32, 8)>>>(w_o, wot_p, NH * HD, HID);

    // 1) QKV projection
    gemm_nt<<<dim3(NQKV / 128, TOK / 128), 256, gemm_smem>>>(hidden, wqkvt_p, qkv_p, TOK, NQKV, HID);

    // 2) RMSNorm + RoPE + split (emits tf32 Q-prescaled / K / V)
    norm_rope_kernel<<<dim3(TOK, 40), 128>>>(qkv_p, cosb, sinb, q_w, k_w, qt_p, kt_p, vt_p);

    // 3) causal GQA attention: 4 heads/CTA, cp.async KV pipeline
    attn_tc3<<<dim3(32, 8, BATCH), 512, attn_smem>>>(qt_p, kt_p, vt_p);

    // 4) output projection
    gemm_nt<<<dim3(HID / 128, TOK / 128), 256, gemm_smem>>>(ctx_p, wot_p, out, TOK, HID, NH * HD);

    (void)in_sizes; (void)n_in; (void)out_size;
}